// round 5
// baseline (speedup 1.0000x reference)
#include <cuda_runtime.h>
#include <math.h>

// ---------------- problem constants ----------------
#define B_    4
#define T_    2048
#define C_    1024
#define NH_   16
#define HD_   64
#define M_    (B_*T_)        // 8192 rows
#define FF_   (4*C_)         // 4096

// ---------------- scratch (static device globals; no allocation) ----------------
__device__ float g_h [M_*C_];
__device__ float g_q [M_*C_];
__device__ float g_k [M_*C_];
__device__ float g_v [M_*C_];
__device__ float g_o [M_*C_];
__device__ float g_x2[M_*C_];
__device__ float g_a [M_*FF_];
__device__ float g_b [M_*FF_];

// ---------------- RMSNorm ----------------
__global__ __launch_bounds__(256) void rmsnorm_k(const float* __restrict__ x,
                                                 const float* __restrict__ g,
                                                 float* __restrict__ out)
{
    int row = blockIdx.x;
    const float* xr = x + (size_t)row * C_;
    float4 v = *(const float4*)(xr + threadIdx.x * 4);
    float ss = v.x*v.x + v.y*v.y + v.z*v.z + v.w*v.w;
    #pragma unroll
    for (int o = 16; o; o >>= 1) ss += __shfl_xor_sync(0xffffffffu, ss, o);
    __shared__ float wsum[8];
    if ((threadIdx.x & 31) == 0) wsum[threadIdx.x >> 5] = ss;
    __syncthreads();
    float s = 0.f;
    #pragma unroll
    for (int i = 0; i < 8; i++) s += wsum[i];
    float inv = rsqrtf(s * (1.0f / C_) + 1e-6f);
    const float4 gv = *(const float4*)(g + threadIdx.x * 4);
    float4 o4;
    o4.x = v.x * inv * gv.x;
    o4.y = v.y * inv * gv.y;
    o4.z = v.z * inv * gv.z;
    o4.w = v.w * inv * gv.w;
    *(float4*)(out + (size_t)row * C_ + threadIdx.x * 4) = o4;
}

// ---------------- SGEMM: C = A[MxK] * B[KxN] (+ optional residual R) ----------------
#define BM 128
#define BN 128
#define BK 8
__global__ __launch_bounds__(256) void sgemm_k(const float* __restrict__ A,
                                               const float* __restrict__ Bw,
                                               const float* __restrict__ R,
                                               float* __restrict__ Cout,
                                               int M, int N, int K)
{
    __shared__ __align__(16) float As[BK][BM];
    __shared__ __align__(16) float Bs[BK][BN];

    int tid  = threadIdx.x;
    int brow = blockIdx.y;   // M tile
    int bcol = blockIdx.x;   // N tile

    const float* Ab = A  + (size_t)brow * BM * K;
    const float* Bb = Bw + (size_t)bcol * BN;

    int arow  = tid >> 1;          // 0..127
    int acol4 = (tid & 1) * 4;     // 0 or 4
    int brw   = tid >> 5;          // 0..7
    int bcol4 = (tid & 31) * 4;    // 0..124

    int ty = tid >> 4;             // 0..15  -> m0 = ty*8
    int tx = tid & 15;             // 0..15  -> n0 = tx*8

    float acc[8][8];
    #pragma unroll
    for (int i = 0; i < 8; i++)
        #pragma unroll
        for (int j = 0; j < 8; j++) acc[i][j] = 0.f;

    for (int k0 = 0; k0 < K; k0 += BK) {
        float4 av = *(const float4*)(Ab + (size_t)arow * K + k0 + acol4);
        As[acol4 + 0][arow] = av.x;
        As[acol4 + 1][arow] = av.y;
        As[acol4 + 2][arow] = av.z;
        As[acol4 + 3][arow] = av.w;
        float4 bv = *(const float4*)(Bb + (size_t)(k0 + brw) * N + bcol4);
        *(float4*)&Bs[brw][bcol4] = bv;
        __syncthreads();

        #pragma unroll
        for (int kk = 0; kk < BK; kk++) {
            float ar[8], br[8];
            *(float4*)&ar[0] = *(const float4*)&As[kk][ty * 8];
            *(float4*)&ar[4] = *(const float4*)&As[kk][ty * 8 + 4];
            *(float4*)&br[0] = *(const float4*)&Bs[kk][tx * 8];
            *(float4*)&br[4] = *(const float4*)&Bs[kk][tx * 8 + 4];
            #pragma unroll
            for (int i = 0; i < 8; i++)
                #pragma unroll
                for (int j = 0; j < 8; j++)
                    acc[i][j] += ar[i] * br[j];
        }
        __syncthreads();
    }

    int row0 = brow * BM + ty * 8;
    int col0 = bcol * BN + tx * 8;
    #pragma unroll
    for (int i = 0; i < 8; i++) {
        size_t off = (size_t)(row0 + i) * N + col0;
        if (R != nullptr) {
            float4 r0 = *(const float4*)(R + off);
            float4 r1 = *(const float4*)(R + off + 4);
            float4 s0, s1;
            s0.x = acc[i][0] + r0.x; s0.y = acc[i][1] + r0.y;
            s0.z = acc[i][2] + r0.z; s0.w = acc[i][3] + r0.w;
            s1.x = acc[i][4] + r1.x; s1.y = acc[i][5] + r1.y;
            s1.z = acc[i][6] + r1.z; s1.w = acc[i][7] + r1.w;
            *(float4*)(Cout + off)     = s0;
            *(float4*)(Cout + off + 4) = s1;
        } else {
            float4 s0, s1;
            s0.x = acc[i][0]; s0.y = acc[i][1]; s0.z = acc[i][2]; s0.w = acc[i][3];
            s1.x = acc[i][4]; s1.y = acc[i][5]; s1.z = acc[i][6]; s1.w = acc[i][7];
            *(float4*)(Cout + off)     = s0;
            *(float4*)(Cout + off + 4) = s1;
        }
    }
}

// ---------------- RoPE (in-place on q and k) ----------------
// Angle = fp32(t) * fp32(inv_freq)  (fp32 product rounding matches reference's
// fp32 outer()); sin/cos evaluated in double of that fp32 angle for accuracy.
__global__ __launch_bounds__(256) void rope_k(float* __restrict__ q, float* __restrict__ k)
{
    int gid = blockIdx.x * blockDim.x + threadIdx.x;  // < M_ * NH_ * 32
    int d  = gid & 31;
    int hh = (gid >> 5) & (NH_ - 1);
    int m  = gid >> 9;
    int t  = m & (T_ - 1);

    double e    = (double)(2 * d) / 64.0;
    float  invf = (float)exp(-e * log(10000.0));   // fp32-rounded inv_freq
    float  angf = (float)t * invf;                 // fp32 product (matches ref rounding)
    double s_d, c_d;
    sincos((double)angf, &s_d, &c_d);
    float cs = (float)c_d, sn = (float)s_d;

    size_t base = (size_t)m * C_ + hh * HD_ + d;
    float q1 = q[base], q2 = q[base + 32];
    q[base]      = q1 * cs - q2 * sn;
    q[base + 32] = q2 * cs + q1 * sn;
    float k1 = k[base], k2 = k[base + 32];
    k[base]      = k1 * cs - k2 * sn;
    k[base + 32] = k2 * cs + k1 * sn;
}

// ---------------- Row-streaming causal attention ----------------
// One thread per query row. q-row and o-row in registers; K/V tiles (64 x 64)
// staged in smem, read via broadcast LDS.128. Lazy online softmax per thread:
// no cross-thread state at all.
#define AT_ROWS 128
#define AT_TS   64
__global__ __launch_bounds__(AT_ROWS) void attn_row_k(const float* __restrict__ q,
                                                      const float* __restrict__ k,
                                                      const float* __restrict__ v,
                                                      float* __restrict__ o)
{
    __shared__ __align__(16) float Ks[AT_TS][68];
    __shared__ __align__(16) float Vs[AT_TS][68];

    int bh = blockIdx.y;
    int b  = bh >> 4;
    int h  = bh & (NH_ - 1);
    int rt = blockIdx.x;                    // row tile of 128
    int t  = rt * AT_ROWS + threadIdx.x;    // this thread's query row (local to (b,h))

    const float scale = 0.125f;             // 1/sqrt(64)
    const float* kbase = k + (size_t)b * T_ * C_ + h * HD_;
    const float* vbase = v + (size_t)b * T_ * C_ + h * HD_;
    const float* qrow  = q + (size_t)(b * T_ + t) * C_ + h * HD_;

    float qreg[HD_];
    #pragma unroll
    for (int dg = 0; dg < HD_; dg += 4) {
        float4 qq = *(const float4*)(qrow + dg);
        qreg[dg + 0] = qq.x * scale;
        qreg[dg + 1] = qq.y * scale;
        qreg[dg + 2] = qq.z * scale;
        qreg[dg + 3] = qq.w * scale;
    }

    float m_r = -1e30f, l_r = 0.f;
    float oa[HD_];
    #pragma unroll
    for (int dg = 0; dg < HD_; dg++) oa[dg] = 0.f;

    int maxjt = (rt * AT_ROWS + AT_ROWS - 1) >> 6;   // block-uniform tile bound

    for (int jt = 0; jt <= maxjt; jt++) {
        __syncthreads();
        // cooperative K/V tile load: 64 rows x 64 floats each
        #pragma unroll
        for (int p = 0; p < 8; p++) {
            int f  = threadIdx.x + AT_ROWS * p;   // 0..1023 float4 slots
            int r  = f >> 4;
            int dg = (f & 15) * 4;
            float4 kk = *(const float4*)(kbase + (size_t)(jt * AT_TS + r) * C_ + dg);
            *(float4*)&Ks[r][dg] = kk;
            float4 vv = *(const float4*)(vbase + (size_t)(jt * AT_TS + r) * C_ + dg);
            *(float4*)&Vs[r][dg] = vv;
        }
        __syncthreads();

        int slim = t - (jt << 6);                 // causal: s_local <= slim
        if (slim > AT_TS - 1) slim = AT_TS - 1;

        for (int s = 0; s <= slim; s++) {
            float dot = 0.f;
            #pragma unroll
            for (int dg = 0; dg < HD_; dg += 4) {
                float4 kk = *(const float4*)&Ks[s][dg];
                dot += qreg[dg + 0] * kk.x + qreg[dg + 1] * kk.y
                     + qreg[dg + 2] * kk.z + qreg[dg + 3] * kk.w;
            }
            if (dot <= m_r) {
                float p = __expf(dot - m_r);
                l_r += p;
                #pragma unroll
                for (int dg = 0; dg < HD_; dg += 4) {
                    float4 vv = *(const float4*)&Vs[s][dg];
                    oa[dg + 0] += p * vv.x;
                    oa[dg + 1] += p * vv.y;
                    oa[dg + 2] += p * vv.z;
                    oa[dg + 3] += p * vv.w;
                }
            } else {
                float r = __expf(m_r - dot);
                m_r = dot;
                l_r = l_r * r + 1.0f;
                #pragma unroll
                for (int dg = 0; dg < HD_; dg += 4) {
                    float4 vv = *(const float4*)&Vs[s][dg];
                    oa[dg + 0] = oa[dg + 0] * r + vv.x;
                    oa[dg + 1] = oa[dg + 1] * r + vv.y;
                    oa[dg + 2] = oa[dg + 2] * r + vv.z;
                    oa[dg + 3] = oa[dg + 3] * r + vv.w;
                }
            }
        }
    }

    float invl = 1.0f / l_r;
    float* orow = o + (size_t)(b * T_ + t) * C_ + h * HD_;
    #pragma unroll
    for (int dg = 0; dg < HD_; dg += 4) {
        float4 res;
        res.x = oa[dg + 0] * invl;
        res.y = oa[dg + 1] * invl;
        res.z = oa[dg + 2] * invl;
        res.w = oa[dg + 3] * invl;
        *(float4*)(orow + dg) = res;
    }
}

// ---------------- SiLU(a) * b -> a ----------------
__global__ __launch_bounds__(256) void silu_mul_k(float* __restrict__ a,
                                                  const float* __restrict__ b)
{
    int i = blockIdx.x * blockDim.x + threadIdx.x;
    float4 av = ((const float4*)a)[i];
    float4 bv = ((const float4*)b)[i];
    av.x = av.x / (1.0f + expf(-av.x)) * bv.x;
    av.y = av.y / (1.0f + expf(-av.y)) * bv.y;
    av.z = av.z / (1.0f + expf(-av.z)) * bv.z;
    av.w = av.w / (1.0f + expf(-av.w)) * bv.w;
    ((float4*)a)[i] = av;
}

// ---------------- launch ----------------
extern "C" void kernel_launch(void* const* d_in, const int* in_sizes, int n_in,
                              void* d_out, int out_size)
{
    const float* x  = (const float*)d_in[0];
    // d_in[1] = mask (int32 tril) -- causality handled analytically
    const float* g1 = (const float*)d_in[2];
    const float* wq = (const float*)d_in[3];
    const float* wk = (const float*)d_in[4];
    const float* wv = (const float*)d_in[5];
    const float* wo = (const float*)d_in[6];
    const float* g2 = (const float*)d_in[7];
    const float* w1 = (const float*)d_in[8];
    const float* w2 = (const float*)d_in[9];
    const float* w3 = (const float*)d_in[10];
    float* out = (float*)d_out;

    float *h, *q, *k, *v, *o, *x2, *a, *bb;
    cudaGetSymbolAddress((void**)&h,  g_h);
    cudaGetSymbolAddress((void**)&q,  g_q);
    cudaGetSymbolAddress((void**)&k,  g_k);
    cudaGetSymbolAddress((void**)&v,  g_v);
    cudaGetSymbolAddress((void**)&o,  g_o);
    cudaGetSymbolAddress((void**)&x2, g_x2);
    cudaGetSymbolAddress((void**)&a,  g_a);
    cudaGetSymbolAddress((void**)&bb, g_b);

    // 1. h = rmsnorm(x, g1)
    rmsnorm_k<<<M_, 256>>>(x, g1, h);

    // 2. q,k,v = h @ {wq,wk,wv}
    dim3 gC(C_ / BN, M_ / BM);
    sgemm_k<<<gC, 256>>>(h, wq, nullptr, q, M_, C_, C_);
    sgemm_k<<<gC, 256>>>(h, wk, nullptr, k, M_, C_, C_);
    sgemm_k<<<gC, 256>>>(h, wv, nullptr, v, M_, C_, C_);

    // 3. RoPE on q, k
    rope_k<<<(M_ * NH_ * 32) / 256, 256>>>(q, k);

    // 4. causal attention -> o (row-streaming, per-thread state only)
    attn_row_k<<<dim3(T_ / AT_ROWS, B_ * NH_), AT_ROWS>>>(q, k, v, o);

    // 5. x2 = x + o @ wo
    sgemm_k<<<gC, 256>>>(o, wo, x, x2, M_, C_, C_);

    // 6. h2 = rmsnorm(x2, g2)
    rmsnorm_k<<<M_, 256>>>(x2, g2, h);

    // 7. a = h2 @ w1 ; bb = h2 @ w3 ; a = silu(a) * bb
    dim3 gF(FF_ / BN, M_ / BM);
    sgemm_k<<<gF, 256>>>(h, w1, nullptr, a, M_, FF_, C_);
    sgemm_k<<<gF, 256>>>(h, w3, nullptr, bb, M_, FF_, C_);
    silu_mul_k<<<(M_ * FF_ / 4) / 256, 256>>>(a, bb);

    // 8. out = x2 + a @ w2
    sgemm_k<<<gC, 256>>>(a, w2, x2, out, M_, C_, FF_);
}

// round 11
// speedup vs baseline: 2.0122x; 2.0122x over previous
#include <cuda_runtime.h>
#include <cuda_bf16.h>
#include <math.h>
#include <cstdint>

// ---------------- problem constants ----------------
#define B_    4
#define T_    2048
#define C_    1024
#define NH_   16
#define HD_   64
#define M_    (B_*T_)        // 8192 rows
#define FF_   (4*C_)         // 4096

// ---------------- scratch (static device globals; no allocation) ----------------
__device__ float g_q [M_*C_];
__device__ float g_k [M_*C_];
__device__ float g_v [M_*C_];
__device__ float g_x2[M_*C_];
__device__ float g_a [M_*FF_];
__device__ float g_b [M_*FF_];
// split activations (bf16 hi/lo)
__device__ __nv_bfloat16 g_hh[M_*C_],  g_hl[M_*C_];    // rmsnorm out
__device__ __nv_bfloat16 g_oh[M_*C_],  g_ol[M_*C_];    // attention out
__device__ __nv_bfloat16 g_sh[M_*FF_], g_sl[M_*FF_];   // silu*w3 out
// transposed + hi/lo-split weights: [N,K] bf16.
#define WOFF_Q  0
#define WOFF_K  (1u<<20)
#define WOFF_V  (2u<<20)
#define WOFF_O  (3u<<20)
#define WOFF_1  (4u<<20)
#define WOFF_3  (8u<<20)
#define WOFF_2  (12u<<20)
__device__ __nv_bfloat16 g_wth[16u<<20];
__device__ __nv_bfloat16 g_wtl[16u<<20];

// ================= helpers =================
__device__ __forceinline__ uint32_t smem_u32(const void* p) {
    uint32_t a;
    asm("{ .reg .u64 t; cvta.to.shared.u64 t, %1; cvt.u32.u64 %0, t; }" : "=r"(a) : "l"(p));
    return a;
}
__device__ __forceinline__ void split2(float a, float b, uint32_t& hw, uint32_t& lw) {
    __nv_bfloat16 ha = __float2bfloat16_rn(a);
    __nv_bfloat16 hb = __float2bfloat16_rn(b);
    hw = (uint32_t)__bfloat16_as_ushort(ha) | ((uint32_t)__bfloat16_as_ushort(hb) << 16);
    __nv_bfloat16 la = __float2bfloat16_rn(a - __bfloat162float(ha));
    __nv_bfloat16 lb = __float2bfloat16_rn(b - __bfloat162float(hb));
    lw = (uint32_t)__bfloat16_as_ushort(la) | ((uint32_t)__bfloat16_as_ushort(lb) << 16);
}

#define LDSM_X4(r0, r1, r2, r3, addr) \
    asm volatile("ldmatrix.sync.aligned.m8n8.x4.shared.b16 {%0,%1,%2,%3}, [%4];" \
        : "=r"(r0), "=r"(r1), "=r"(r2), "=r"(r3) : "r"(addr))

#define MMA_BF16(c, a, b0, b1) \
    asm volatile("mma.sync.aligned.m16n8k16.row.col.f32.bf16.bf16.f32 " \
        "{%0,%1,%2,%3}, {%4,%5,%6,%7}, {%8,%9}, {%0,%1,%2,%3};" \
        : "+f"((c)[0]), "+f"((c)[1]), "+f"((c)[2]), "+f"((c)[3]) \
        : "r"((a)[0]), "r"((a)[1]), "r"((a)[2]), "r"((a)[3]), "r"(b0), "r"(b1))

// ================= weight transpose + hi/lo split =================
// W[K,N] fp32 row-major -> Th/Tl [N,K] bf16
__global__ __launch_bounds__(256) void wsplit_k(const float* __restrict__ W,
                                                __nv_bfloat16* __restrict__ Th,
                                                __nv_bfloat16* __restrict__ Tl,
                                                int K, int N)
{
    __shared__ float tile[32][33];
    int bx = blockIdx.x;   // N/32
    int by = blockIdx.y;   // K/32
    int tx = threadIdx.x;  // 0..31
    int ty = threadIdx.y;  // 0..7
    #pragma unroll
    for (int i = 0; i < 32; i += 8)
        tile[ty + i][tx] = W[(size_t)(by * 32 + ty + i) * N + bx * 32 + tx];
    __syncthreads();
    #pragma unroll
    for (int i = 0; i < 32; i += 8) {
        float v = tile[tx][ty + i];
        size_t o = (size_t)(bx * 32 + ty + i) * K + by * 32 + tx;
        __nv_bfloat16 h = __float2bfloat16_rn(v);
        Th[o] = h;
        Tl[o] = __float2bfloat16_rn(v - __bfloat162float(h));
    }
}

// ================= split-bf16 HMMA GEMM =================
// C[M,N] = (Ah+Al)[M,K] @ (Bh+Bl)[N,K]^T  (3-term), optional residual R.
// CTA 128x128, 8 warps (2m x 4n), warp tile 64x32, K-chunk 64.
// smem rows padded to 144B (conflict-free ldmatrix, 16B-aligned).
#define RS 144
#define TILE_B (128*RS)                 // 18432 B per tile
#define TG_SMEM (4*TILE_B)              // 73728 B
__global__ __launch_bounds__(256, 2) void tgemm_k(const __nv_bfloat16* __restrict__ Ath,
                                                  const __nv_bfloat16* __restrict__ Atl,
                                                  const __nv_bfloat16* __restrict__ Bth,
                                                  const __nv_bfloat16* __restrict__ Btl,
                                                  const float* __restrict__ R,
                                                  float* __restrict__ Cout,
                                                  int M, int N, int K)
{
    extern __shared__ __align__(16) char smem[];
    uint32_t sb = smem_u32(smem);
    const int SM_AH = 0, SM_AL = TILE_B, SM_BH = 2*TILE_B, SM_BL = 3*TILE_B;

    int tid  = threadIdx.x;
    int lane = tid & 31;
    int wid  = tid >> 5;
    int brow = blockIdx.y;
    int bcol = blockIdx.x;
    int wm = (wid >> 2) * 64;
    int wn = (wid & 3) * 32;

    float acc[4][4][4];
    #pragma unroll
    for (int i = 0; i < 4; i++)
        #pragma unroll
        for (int j = 0; j < 4; j++)
            #pragma unroll
            for (int r = 0; r < 4; r++) acc[i][j][r] = 0.f;

    int nchunks = K >> 6;
    for (int ch = 0; ch < nchunks; ch++) {
        __syncthreads();
        // ---- load 4 tiles (128 rows x 64 bf16 each) ----
        #pragma unroll
        for (int p = 0; p < 4; p++) {
            int f = tid + 256 * p;      // 0..1023 uint4 slots per tile
            int r = f >> 3;
            int j = f & 7;
            size_t ga = (size_t)(brow * 128 + r) * K + ch * 64 + j * 8;
            size_t gb = (size_t)(bcol * 128 + r) * K + ch * 64 + j * 8;
            uint32_t d = r * RS + j * 16;
            *(uint4*)(smem + SM_AH + d) = *(const uint4*)(Ath + ga);
            *(uint4*)(smem + SM_AL + d) = *(const uint4*)(Atl + ga);
            *(uint4*)(smem + SM_BH + d) = *(const uint4*)(Bth + gb);
            *(uint4*)(smem + SM_BL + d) = *(const uint4*)(Btl + gb);
        }
        __syncthreads();

        #pragma unroll
        for (int ks = 0; ks < 4; ks++) {
            // B fragments for n32: two x4 loads per (hi, lo)
            uint32_t bh[8], bl[8];
            #pragma unroll
            for (int nt2 = 0; nt2 < 2; nt2++) {
                int nrow = wn + nt2 * 16 + (lane & 7) + ((lane >> 4) << 3);
                uint32_t ba = sb + SM_BH + nrow * RS + ks * 32 + ((lane >> 3) & 1) * 16;
                LDSM_X4(bh[nt2*4+0], bh[nt2*4+1], bh[nt2*4+2], bh[nt2*4+3], ba);
                LDSM_X4(bl[nt2*4+0], bl[nt2*4+1], bl[nt2*4+2], bl[nt2*4+3], ba + TILE_B);
            }
            #pragma unroll
            for (int mt = 0; mt < 4; mt++) {
                int mrow = wm + mt * 16 + (lane & 15);
                uint32_t aa = sb + SM_AH + mrow * RS + ks * 32 + (lane >> 4) * 16;
                uint32_t ah[4], al[4];
                LDSM_X4(ah[0], ah[1], ah[2], ah[3], aa);
                LDSM_X4(al[0], al[1], al[2], al[3], aa + TILE_B);
                #pragma unroll
                for (int nt = 0; nt < 4; nt++) {
                    int bi = (nt >> 1) * 4 + (nt & 1) * 2;
                    MMA_BF16(acc[mt][nt], ah, bh[bi], bh[bi+1]);
                    MMA_BF16(acc[mt][nt], ah, bl[bi], bl[bi+1]);
                    MMA_BF16(acc[mt][nt], al, bh[bi], bh[bi+1]);
                }
            }
        }
    }

    // ---- epilogue: c-frag rows lane>>2 (+8), cols (lane&3)*2 ----
    #pragma unroll
    for (int mt = 0; mt < 4; mt++) {
        #pragma unroll
        for (int nt = 0; nt < 4; nt++) {
            int r0 = brow * 128 + wm + mt * 16 + (lane >> 2);
            int c0 = bcol * 128 + wn + nt * 8 + (lane & 3) * 2;
            size_t o1 = (size_t)r0 * N + c0;
            size_t o2 = o1 + (size_t)8 * N;
            float2 d0 = make_float2(acc[mt][nt][0], acc[mt][nt][1]);
            float2 d1 = make_float2(acc[mt][nt][2], acc[mt][nt][3]);
            if (R != nullptr) {
                float2 r1 = *(const float2*)(R + o1);
                float2 r2 = *(const float2*)(R + o2);
                d0.x += r1.x; d0.y += r1.y;
                d1.x += r2.x; d1.y += r2.y;
            }
            *(float2*)(Cout + o1) = d0;
            *(float2*)(Cout + o2) = d1;
        }
    }
}

// ---------------- RMSNorm -> split bf16 hi/lo ----------------
__global__ __launch_bounds__(256) void rmsnorm_split_k(const float* __restrict__ x,
                                                       const float* __restrict__ g,
                                                       __nv_bfloat16* __restrict__ outh,
                                                       __nv_bfloat16* __restrict__ outl)
{
    int row = blockIdx.x;
    const float* xr = x + (size_t)row * C_;
    float4 v = *(const float4*)(xr + threadIdx.x * 4);
    float ss = v.x*v.x + v.y*v.y + v.z*v.z + v.w*v.w;
    #pragma unroll
    for (int o = 16; o; o >>= 1) ss += __shfl_xor_sync(0xffffffffu, ss, o);
    __shared__ float wsum[8];
    if ((threadIdx.x & 31) == 0) wsum[threadIdx.x >> 5] = ss;
    __syncthreads();
    float s = 0.f;
    #pragma unroll
    for (int i = 0; i < 8; i++) s += wsum[i];
    float inv = rsqrtf(s * (1.0f / C_) + 1e-6f);
    const float4 gv = *(const float4*)(g + threadIdx.x * 4);
    float y0 = v.x * inv * gv.x;
    float y1 = v.y * inv * gv.y;
    float y2 = v.z * inv * gv.z;
    float y3 = v.w * inv * gv.w;
    uint32_t h0, l0, h1, l1;
    split2(y0, y1, h0, l0);
    split2(y2, y3, h1, l1);
    size_t off = (size_t)row * C_ + threadIdx.x * 4;
    *(uint2*)(outh + off) = make_uint2(h0, h1);
    *(uint2*)(outl + off) = make_uint2(l0, l1);
}

// ---------------- RoPE (in-place on q and k) ----------------
__global__ __launch_bounds__(256) void rope_k(float* __restrict__ q, float* __restrict__ k)
{
    int gid = blockIdx.x * blockDim.x + threadIdx.x;  // < M_ * NH_ * 32
    int d  = gid & 31;
    int hh = (gid >> 5) & (NH_ - 1);
    int m  = gid >> 9;
    int t  = m & (T_ - 1);

    double e    = (double)(2 * d) / 64.0;
    float  invf = (float)exp(-e * log(10000.0));
    float  angf = (float)t * invf;
    double s_d, c_d;
    sincos((double)angf, &s_d, &c_d);
    float cs = (float)c_d, sn = (float)s_d;

    size_t base = (size_t)m * C_ + hh * HD_ + d;
    float q1 = q[base], q2 = q[base + 32];
    q[base]      = q1 * cs - q2 * sn;
    q[base + 32] = q2 * cs + q1 * sn;
    float k1 = k[base], k2 = k[base + 32];
    k[base]      = k1 * cs - k2 * sn;
    k[base + 32] = k2 * cs + k1 * sn;
}

// ---------------- Row-streaming causal attention -> split bf16 out ----------------
#define AT_ROWS 128
#define AT_TS   64
__global__ __launch_bounds__(AT_ROWS) void attn_row_k(const float* __restrict__ q,
                                                      const float* __restrict__ k,
                                                      const float* __restrict__ v,
                                                      __nv_bfloat16* __restrict__ oh,
                                                      __nv_bfloat16* __restrict__ ol)
{
    __shared__ __align__(16) float Ks[AT_TS][68];
    __shared__ __align__(16) float Vs[AT_TS][68];

    int bh = blockIdx.y;
    int b  = bh >> 4;
    int h  = bh & (NH_ - 1);
    int rt = blockIdx.x;
    int t  = rt * AT_ROWS + threadIdx.x;

    const float scale = 0.125f;
    const float* kbase = k + (size_t)b * T_ * C_ + h * HD_;
    const float* vbase = v + (size_t)b * T_ * C_ + h * HD_;
    const float* qrow  = q + (size_t)(b * T_ + t) * C_ + h * HD_;

    float qreg[HD_];
    #pragma unroll
    for (int dg = 0; dg < HD_; dg += 4) {
        float4 qq = *(const float4*)(qrow + dg);
        qreg[dg + 0] = qq.x * scale;
        qreg[dg + 1] = qq.y * scale;
        qreg[dg + 2] = qq.z * scale;
        qreg[dg + 3] = qq.w * scale;
    }

    float m_r = -1e30f, l_r = 0.f;
    float oa[HD_];
    #pragma unroll
    for (int dg = 0; dg < HD_; dg++) oa[dg] = 0.f;

    int maxjt = (rt * AT_ROWS + AT_ROWS - 1) >> 6;

    for (int jt = 0; jt <= maxjt; jt++) {
        __syncthreads();
        #pragma unroll
        for (int p = 0; p < 8; p++) {
            int f  = threadIdx.x + AT_ROWS * p;
            int r  = f >> 4;
            int dg = (f & 15) * 4;
            float4 kk = *(const float4*)(kbase + (size_t)(jt * AT_TS + r) * C_ + dg);
            *(float4*)&Ks[r][dg] = kk;
            float4 vv = *(const float4*)(vbase + (size_t)(jt * AT_TS + r) * C_ + dg);
            *(float4*)&Vs[r][dg] = vv;
        }
        __syncthreads();

        int slim = t - (jt << 6);
        if (slim > AT_TS - 1) slim = AT_TS - 1;

        for (int s = 0; s <= slim; s++) {
            float dot = 0.f;
            #pragma unroll
            for (int dg = 0; dg < HD_; dg += 4) {
                float4 kk = *(const float4*)&Ks[s][dg];
                dot += qreg[dg + 0] * kk.x + qreg[dg + 1] * kk.y
                     + qreg[dg + 2] * kk.z + qreg[dg + 3] * kk.w;
            }
            if (dot <= m_r) {
                float p = __expf(dot - m_r);
                l_r += p;
                #pragma unroll
                for (int dg = 0; dg < HD_; dg += 4) {
                    float4 vv = *(const float4*)&Vs[s][dg];
                    oa[dg + 0] += p * vv.x;
                    oa[dg + 1] += p * vv.y;
                    oa[dg + 2] += p * vv.z;
                    oa[dg + 3] += p * vv.w;
                }
            } else {
                float r = __expf(m_r - dot);
                m_r = dot;
                l_r = l_r * r + 1.0f;
                #pragma unroll
                for (int dg = 0; dg < HD_; dg += 4) {
                    float4 vv = *(const float4*)&Vs[s][dg];
                    oa[dg + 0] = oa[dg + 0] * r + vv.x;
                    oa[dg + 1] = oa[dg + 1] * r + vv.y;
                    oa[dg + 2] = oa[dg + 2] * r + vv.z;
                    oa[dg + 3] = oa[dg + 3] * r + vv.w;
                }
            }
        }
    }

    float invl = 1.0f / l_r;
    size_t obase = (size_t)(b * T_ + t) * C_ + h * HD_;
    #pragma unroll
    for (int dg = 0; dg < HD_; dg += 4) {
        float y0 = oa[dg + 0] * invl;
        float y1 = oa[dg + 1] * invl;
        float y2 = oa[dg + 2] * invl;
        float y3 = oa[dg + 3] * invl;
        uint32_t h0, l0, h1, l1;
        split2(y0, y1, h0, l0);
        split2(y2, y3, h1, l1);
        *(uint2*)(oh + obase + dg) = make_uint2(h0, h1);
        *(uint2*)(ol + obase + dg) = make_uint2(l0, l1);
    }
}

// ---------------- SiLU(a) * b -> split bf16 hi/lo ----------------
__global__ __launch_bounds__(256) void silu_mul_split_k(const float* __restrict__ a,
                                                        const float* __restrict__ b,
                                                        __nv_bfloat16* __restrict__ sh,
                                                        __nv_bfloat16* __restrict__ sl)
{
    int i = blockIdx.x * blockDim.x + threadIdx.x;
    float4 av = ((const float4*)a)[i];
    float4 bv = ((const float4*)b)[i];
    float y0 = av.x / (1.0f + expf(-av.x)) * bv.x;
    float y1 = av.y / (1.0f + expf(-av.y)) * bv.y;
    float y2 = av.z / (1.0f + expf(-av.z)) * bv.z;
    float y3 = av.w / (1.0f + expf(-av.w)) * bv.w;
    uint32_t h0, l0, h1, l1;
    split2(y0, y1, h0, l0);
    split2(y2, y3, h1, l1);
    size_t off = (size_t)i * 4;
    *(uint2*)(sh + off) = make_uint2(h0, h1);
    *(uint2*)(sl + off) = make_uint2(l0, l1);
}

// ---------------- launch ----------------
extern "C" void kernel_launch(void* const* d_in, const int* in_sizes, int n_in,
                              void* d_out, int out_size)
{
    const float* x  = (const float*)d_in[0];
    const float* g1 = (const float*)d_in[2];
    const float* wq = (const float*)d_in[3];
    const float* wk = (const float*)d_in[4];
    const float* wv = (const float*)d_in[5];
    const float* wo = (const float*)d_in[6];
    const float* g2 = (const float*)d_in[7];
    const float* w1 = (const float*)d_in[8];
    const float* w2 = (const float*)d_in[9];
    const float* w3 = (const float*)d_in[10];
    float* out = (float*)d_out;

    float *q, *k, *v, *x2, *a, *bb;
    __nv_bfloat16 *wth, *wtl, *hh, *hl, *oh, *ol, *sh, *sl;
    cudaGetSymbolAddress((void**)&q,   g_q);
    cudaGetSymbolAddress((void**)&k,   g_k);
    cudaGetSymbolAddress((void**)&v,   g_v);
    cudaGetSymbolAddress((void**)&x2,  g_x2);
    cudaGetSymbolAddress((void**)&a,   g_a);
    cudaGetSymbolAddress((void**)&bb,  g_b);
    cudaGetSymbolAddress((void**)&wth, g_wth);
    cudaGetSymbolAddress((void**)&wtl, g_wtl);
    cudaGetSymbolAddress((void**)&hh,  g_hh);
    cudaGetSymbolAddress((void**)&hl,  g_hl);
    cudaGetSymbolAddress((void**)&oh,  g_oh);
    cudaGetSymbolAddress((void**)&ol,  g_ol);
    cudaGetSymbolAddress((void**)&sh,  g_sh);
    cudaGetSymbolAddress((void**)&sl,  g_sl);

    cudaFuncSetAttribute(tgemm_k, cudaFuncAttributeMaxDynamicSharedMemorySize, TG_SMEM);

    // 0. transpose + hi/lo split all weights
    dim3 wb(32, 8);
    wsplit_k<<<dim3(C_/32,  C_/32),  wb>>>(wq, wth + WOFF_Q, wtl + WOFF_Q, C_,  C_);
    wsplit_k<<<dim3(C_/32,  C_/32),  wb>>>(wk, wth + WOFF_K, wtl + WOFF_K, C_,  C_);
    wsplit_k<<<dim3(C_/32,  C_/32),  wb>>>(wv, wth + WOFF_V, wtl + WOFF_V, C_,  C_);
    wsplit_k<<<dim3(C_/32,  C_/32),  wb>>>(wo, wth + WOFF_O, wtl + WOFF_O, C_,  C_);
    wsplit_k<<<dim3(FF_/32, C_/32),  wb>>>(w1, wth + WOFF_1, wtl + WOFF_1, C_,  FF_);
    wsplit_k<<<dim3(FF_/32, C_/32),  wb>>>(w3, wth + WOFF_3, wtl + WOFF_3, C_,  FF_);
    wsplit_k<<<dim3(C_/32,  FF_/32), wb>>>(w2, wth + WOFF_2, wtl + WOFF_2, FF_, C_);

    // 1. h = rmsnorm(x, g1) -> split
    rmsnorm_split_k<<<M_, 256>>>(x, g1, hh, hl);

    // 2. q,k,v = h @ {wq,wk,wv}
    dim3 gC(C_ / 128, M_ / 128);
    tgemm_k<<<gC, 256, TG_SMEM>>>(hh, hl, wth + WOFF_Q, wtl + WOFF_Q, nullptr, q, M_, C_, C_);
    tgemm_k<<<gC, 256, TG_SMEM>>>(hh, hl, wth + WOFF_K, wtl + WOFF_K, nullptr, k, M_, C_, C_);
    tgemm_k<<<gC, 256, TG_SMEM>>>(hh, hl, wth + WOFF_V, wtl + WOFF_V, nullptr, v, M_, C_, C_);

    // 3. RoPE on q, k
    rope_k<<<(M_ * NH_ * 32) / 256, 256>>>(q, k);

    // 4. causal attention -> split o
    attn_row_k<<<dim3(T_ / AT_ROWS, B_ * NH_), AT_ROWS>>>(q, k, v, oh, ol);

    // 5. x2 = x + o @ wo
    tgemm_k<<<gC, 256, TG_SMEM>>>(oh, ol, wth + WOFF_O, wtl + WOFF_O, x, x2, M_, C_, C_);

    // 6. h2 = rmsnorm(x2, g2) -> split
    rmsnorm_split_k<<<M_, 256>>>(x2, g2, hh, hl);

    // 7. a = h2 @ w1 ; bb = h2 @ w3 ; s = silu(a) * bb -> split
    dim3 gF(FF_ / 128, M_ / 128);
    tgemm_k<<<gF, 256, TG_SMEM>>>(hh, hl, wth + WOFF_1, wtl + WOFF_1, nullptr, a,  M_, FF_, C_);
    tgemm_k<<<gF, 256, TG_SMEM>>>(hh, hl, wth + WOFF_3, wtl + WOFF_3, nullptr, bb, M_, FF_, C_);
    silu_mul_split_k<<<(M_ * FF_ / 4) / 256, 256>>>(a, bb, sh, sl);

    // 8. out = x2 + s @ w2
    tgemm_k<<<gC, 256, TG_SMEM>>>(sh, sl, wth + WOFF_2, wtl + WOFF_2, x2, out, M_, C_, FF_);
}

// round 17
// speedup vs baseline: 2.7852x; 1.3842x over previous
#include <cuda_runtime.h>
#include <cuda_bf16.h>
#include <math.h>
#include <cstdint>

// ---------------- problem constants ----------------
#define B_    4
#define T_    2048
#define C_    1024
#define NH_   16
#define HD_   64
#define M_    (B_*T_)        // 8192 rows
#define FF_   (4*C_)         // 4096

// ---------------- scratch (static device globals; no allocation) ----------------
__device__ float g_q [M_*C_];
__device__ float g_k [M_*C_];
__device__ float g_v [M_*C_];
__device__ float g_x2[M_*C_];
__device__ float g_a [M_*FF_];
__device__ float g_b [M_*FF_];
// split activations (bf16 hi/lo)
__device__ __nv_bfloat16 g_hh[M_*C_],  g_hl[M_*C_];    // rmsnorm out
__device__ __nv_bfloat16 g_oh[M_*C_],  g_ol[M_*C_];    // attention out
__device__ __nv_bfloat16 g_sh[M_*FF_], g_sl[M_*FF_];   // silu*w3 out
// attention operand splits
__device__ __nv_bfloat16 g_qh[M_*C_], g_ql[M_*C_];
__device__ __nv_bfloat16 g_kh[M_*C_], g_kl[M_*C_];
__device__ __nv_bfloat16 g_vth[M_*C_], g_vtl[M_*C_];   // V^T: [bh][hd][T]
// transposed + hi/lo-split weights: [N,K] bf16.
#define WOFF_Q  0
#define WOFF_K  (1u<<20)
#define WOFF_V  (2u<<20)
#define WOFF_O  (3u<<20)
#define WOFF_1  (4u<<20)
#define WOFF_3  (8u<<20)
#define WOFF_2  (12u<<20)
__device__ __nv_bfloat16 g_wth[16u<<20];
__device__ __nv_bfloat16 g_wtl[16u<<20];

// ================= helpers =================
__device__ __forceinline__ uint32_t smem_u32(const void* p) {
    uint32_t a;
    asm("{ .reg .u64 t; cvta.to.shared.u64 t, %1; cvt.u32.u64 %0, t; }" : "=r"(a) : "l"(p));
    return a;
}
__device__ __forceinline__ void split2(float a, float b, uint32_t& hw, uint32_t& lw) {
    __nv_bfloat16 ha = __float2bfloat16_rn(a);
    __nv_bfloat16 hb = __float2bfloat16_rn(b);
    hw = (uint32_t)__bfloat16_as_ushort(ha) | ((uint32_t)__bfloat16_as_ushort(hb) << 16);
    __nv_bfloat16 la = __float2bfloat16_rn(a - __bfloat162float(ha));
    __nv_bfloat16 lb = __float2bfloat16_rn(b - __bfloat162float(hb));
    lw = (uint32_t)__bfloat16_as_ushort(la) | ((uint32_t)__bfloat16_as_ushort(lb) << 16);
}

#define LDSM_X4(r0, r1, r2, r3, addr) \
    asm volatile("ldmatrix.sync.aligned.m8n8.x4.shared.b16 {%0,%1,%2,%3}, [%4];" \
        : "=r"(r0), "=r"(r1), "=r"(r2), "=r"(r3) : "r"(addr))

#define MMA_BF16(c, a, b0, b1) \
    asm volatile("mma.sync.aligned.m16n8k16.row.col.f32.bf16.bf16.f32 " \
        "{%0,%1,%2,%3}, {%4,%5,%6,%7}, {%8,%9}, {%0,%1,%2,%3};" \
        : "+f"((c)[0]), "+f"((c)[1]), "+f"((c)[2]), "+f"((c)[3]) \
        : "r"((a)[0]), "r"((a)[1]), "r"((a)[2]), "r"((a)[3]), "r"(b0), "r"(b1))

// ================= weight transpose + hi/lo split =================
__global__ __launch_bounds__(256) void wsplit_k(const float* __restrict__ W,
                                                __nv_bfloat16* __restrict__ Th,
                                                __nv_bfloat16* __restrict__ Tl,
                                                int K, int N)
{
    __shared__ float tile[32][33];
    int bx = blockIdx.x;   // N/32
    int by = blockIdx.y;   // K/32
    int tx = threadIdx.x;  // 0..31
    int ty = threadIdx.y;  // 0..7
    #pragma unroll
    for (int i = 0; i < 32; i += 8)
        tile[ty + i][tx] = W[(size_t)(by * 32 + ty + i) * N + bx * 32 + tx];
    __syncthreads();
    #pragma unroll
    for (int i = 0; i < 32; i += 8) {
        float v = tile[tx][ty + i];
        size_t o = (size_t)(bx * 32 + ty + i) * K + by * 32 + tx;
        __nv_bfloat16 h = __float2bfloat16_rn(v);
        Th[o] = h;
        Tl[o] = __float2bfloat16_rn(v - __bfloat162float(h));
    }
}

// ================= split-bf16 HMMA GEMM =================
#define RS 144
#define TILE_B (128*RS)
#define TG_SMEM (4*TILE_B)
__global__ __launch_bounds__(256, 2) void tgemm_k(const __nv_bfloat16* __restrict__ Ath,
                                                  const __nv_bfloat16* __restrict__ Atl,
                                                  const __nv_bfloat16* __restrict__ Bth,
                                                  const __nv_bfloat16* __restrict__ Btl,
                                                  const float* __restrict__ R,
                                                  float* __restrict__ Cout,
                                                  int M, int N, int K)
{
    extern __shared__ __align__(16) char smem[];
    uint32_t sb = smem_u32(smem);
    const int SM_AH = 0, SM_AL = TILE_B, SM_BH = 2*TILE_B, SM_BL = 3*TILE_B;

    int tid  = threadIdx.x;
    int lane = tid & 31;
    int wid  = tid >> 5;
    int brow = blockIdx.y;
    int bcol = blockIdx.x;
    int wm = (wid >> 2) * 64;
    int wn = (wid & 3) * 32;

    float acc[4][4][4];
    #pragma unroll
    for (int i = 0; i < 4; i++)
        #pragma unroll
        for (int j = 0; j < 4; j++)
            #pragma unroll
            for (int r = 0; r < 4; r++) acc[i][j][r] = 0.f;

    int nchunks = K >> 6;
    for (int ch = 0; ch < nchunks; ch++) {
        __syncthreads();
        #pragma unroll
        for (int p = 0; p < 4; p++) {
            int f = tid + 256 * p;
            int r = f >> 3;
            int j = f & 7;
            size_t ga = (size_t)(brow * 128 + r) * K + ch * 64 + j * 8;
            size_t gb = (size_t)(bcol * 128 + r) * K + ch * 64 + j * 8;
            uint32_t d = r * RS + j * 16;
            *(uint4*)(smem + SM_AH + d) = *(const uint4*)(Ath + ga);
            *(uint4*)(smem + SM_AL + d) = *(const uint4*)(Atl + ga);
            *(uint4*)(smem + SM_BH + d) = *(const uint4*)(Bth + gb);
            *(uint4*)(smem + SM_BL + d) = *(const uint4*)(Btl + gb);
        }
        __syncthreads();

        #pragma unroll
        for (int ks = 0; ks < 4; ks++) {
            uint32_t bh[8], bl[8];
            #pragma unroll
            for (int nt2 = 0; nt2 < 2; nt2++) {
                int nrow = wn + nt2 * 16 + (lane & 7) + ((lane >> 4) << 3);
                uint32_t ba = sb + SM_BH + nrow * RS + ks * 32 + ((lane >> 3) & 1) * 16;
                LDSM_X4(bh[nt2*4+0], bh[nt2*4+1], bh[nt2*4+2], bh[nt2*4+3], ba);
                LDSM_X4(bl[nt2*4+0], bl[nt2*4+1], bl[nt2*4+2], bl[nt2*4+3], ba + TILE_B);
            }
            #pragma unroll
            for (int mt = 0; mt < 4; mt++) {
                int mrow = wm + mt * 16 + (lane & 15);
                uint32_t aa = sb + SM_AH + mrow * RS + ks * 32 + (lane >> 4) * 16;
                uint32_t ah[4], al[4];
                LDSM_X4(ah[0], ah[1], ah[2], ah[3], aa);
                LDSM_X4(al[0], al[1], al[2], al[3], aa + TILE_B);
                #pragma unroll
                for (int nt = 0; nt < 4; nt++) {
                    int bi = (nt >> 1) * 4 + (nt & 1) * 2;
                    MMA_BF16(acc[mt][nt], ah, bh[bi], bh[bi+1]);
                    MMA_BF16(acc[mt][nt], ah, bl[bi], bl[bi+1]);
                    MMA_BF16(acc[mt][nt], al, bh[bi], bh[bi+1]);
                }
            }
        }
    }

    #pragma unroll
    for (int mt = 0; mt < 4; mt++) {
        #pragma unroll
        for (int nt = 0; nt < 4; nt++) {
            int r0 = brow * 128 + wm + mt * 16 + (lane >> 2);
            int c0 = bcol * 128 + wn + nt * 8 + (lane & 3) * 2;
            size_t o1 = (size_t)r0 * N + c0;
            size_t o2 = o1 + (size_t)8 * N;
            float2 d0 = make_float2(acc[mt][nt][0], acc[mt][nt][1]);
            float2 d1 = make_float2(acc[mt][nt][2], acc[mt][nt][3]);
            if (R != nullptr) {
                float2 r1 = *(const float2*)(R + o1);
                float2 r2 = *(const float2*)(R + o2);
                d0.x += r1.x; d0.y += r1.y;
                d1.x += r2.x; d1.y += r2.y;
            }
            *(float2*)(Cout + o1) = d0;
            *(float2*)(Cout + o2) = d1;
        }
    }
}

// ---------------- RMSNorm -> split bf16 hi/lo ----------------
__global__ __launch_bounds__(256) void rmsnorm_split_k(const float* __restrict__ x,
                                                       const float* __restrict__ g,
                                                       __nv_bfloat16* __restrict__ outh,
                                                       __nv_bfloat16* __restrict__ outl)
{
    int row = blockIdx.x;
    const float* xr = x + (size_t)row * C_;
    float4 v = *(const float4*)(xr + threadIdx.x * 4);
    float ss = v.x*v.x + v.y*v.y + v.z*v.z + v.w*v.w;
    #pragma unroll
    for (int o = 16; o; o >>= 1) ss += __shfl_xor_sync(0xffffffffu, ss, o);
    __shared__ float wsum[8];
    if ((threadIdx.x & 31) == 0) wsum[threadIdx.x >> 5] = ss;
    __syncthreads();
    float s = 0.f;
    #pragma unroll
    for (int i = 0; i < 8; i++) s += wsum[i];
    float inv = rsqrtf(s * (1.0f / C_) + 1e-6f);
    const float4 gv = *(const float4*)(g + threadIdx.x * 4);
    float y0 = v.x * inv * gv.x;
    float y1 = v.y * inv * gv.y;
    float y2 = v.z * inv * gv.z;
    float y3 = v.w * inv * gv.w;
    uint32_t h0, l0, h1, l1;
    split2(y0, y1, h0, l0);
    split2(y2, y3, h1, l1);
    size_t off = (size_t)row * C_ + threadIdx.x * 4;
    *(uint2*)(outh + off) = make_uint2(h0, h1);
    *(uint2*)(outl + off) = make_uint2(l0, l1);
}

// ---------------- RoPE + split (q pre-scaled by 1/8) ----------------
__global__ __launch_bounds__(256) void rope_split_k(const float* __restrict__ q,
                                                    const float* __restrict__ k,
                                                    __nv_bfloat16* __restrict__ qh,
                                                    __nv_bfloat16* __restrict__ ql,
                                                    __nv_bfloat16* __restrict__ kh,
                                                    __nv_bfloat16* __restrict__ kl)
{
    int gid = blockIdx.x * blockDim.x + threadIdx.x;  // < M_ * NH_ * 32
    int d  = gid & 31;
    int hh = (gid >> 5) & (NH_ - 1);
    int m  = gid >> 9;
    int t  = m & (T_ - 1);

    double e    = (double)(2 * d) / 64.0;
    float  invf = (float)exp(-e * log(10000.0));
    float  angf = (float)t * invf;
    double s_d, c_d;
    sincos((double)angf, &s_d, &c_d);
    float cs = (float)c_d, sn = (float)s_d;

    size_t base = (size_t)m * C_ + hh * HD_ + d;
    float q1 = q[base], q2 = q[base + 32];
    float k1 = k[base], k2 = k[base + 32];
    float q1r = (q1 * cs - q2 * sn) * 0.125f;
    float q2r = (q2 * cs + q1 * sn) * 0.125f;
    float k1r = k1 * cs - k2 * sn;
    float k2r = k2 * cs + k1 * sn;

    __nv_bfloat16 t1;
    t1 = __float2bfloat16_rn(q1r); qh[base]      = t1; ql[base]      = __float2bfloat16_rn(q1r - __bfloat162float(t1));
    t1 = __float2bfloat16_rn(q2r); qh[base + 32] = t1; ql[base + 32] = __float2bfloat16_rn(q2r - __bfloat162float(t1));
    t1 = __float2bfloat16_rn(k1r); kh[base]      = t1; kl[base]      = __float2bfloat16_rn(k1r - __bfloat162float(t1));
    t1 = __float2bfloat16_rn(k2r); kh[base + 32] = t1; kl[base + 32] = __float2bfloat16_rn(k2r - __bfloat162float(t1));
}

// ---------------- V transpose + split: v[m][C] -> vt[bh][hd][T] ----------------
__global__ __launch_bounds__(256) void vtsplit_k(const float* __restrict__ v,
                                                 __nv_bfloat16* __restrict__ vh,
                                                 __nv_bfloat16* __restrict__ vl)
{
    __shared__ float tile[32][33];
    int tt = blockIdx.x;        // T/32
    int dt = blockIdx.y;        // HD/32
    int bh = blockIdx.z;
    int b  = bh >> 4;
    int h  = bh & (NH_ - 1);
    int tx = threadIdx.x;       // 0..31
    int ty = threadIdx.y;       // 0..7
    #pragma unroll
    for (int i = 0; i < 32; i += 8)
        tile[ty + i][tx] = v[(size_t)(b * T_ + tt * 32 + ty + i) * C_ + h * HD_ + dt * 32 + tx];
    __syncthreads();
    #pragma unroll
    for (int i = 0; i < 32; i += 8) {
        float val = tile[tx][ty + i];
        size_t o = (size_t)(bh * HD_ + dt * 32 + ty + i) * T_ + tt * 32 + tx;
        __nv_bfloat16 hv = __float2bfloat16_rn(val);
        vh[o] = hv;
        vl[o] = __float2bfloat16_rn(val - __bfloat162float(hv));
    }
}

// ================= split-bf16 HMMA flash attention =================
// CTA: 64 q-rows x one (b,h). 4 warps, warp = m16. kv streamed in 64-col tiles.
#define ATRS  144
#define ATILE (64*ATRS)             // 9216 B
#define AT_SMEM (6*ATILE)           // 55296 B
__global__ __launch_bounds__(128, 4) void attn_mma_k(
    const __nv_bfloat16* __restrict__ qh, const __nv_bfloat16* __restrict__ ql,
    const __nv_bfloat16* __restrict__ kh, const __nv_bfloat16* __restrict__ kl,
    const __nv_bfloat16* __restrict__ vth, const __nv_bfloat16* __restrict__ vtl,
    __nv_bfloat16* __restrict__ oh, __nv_bfloat16* __restrict__ ol)
{
    extern __shared__ __align__(16) char asm_[];
    uint32_t sb = smem_u32(asm_);
    const int SQH = 0, SQL = ATILE, SKH = 2*ATILE, SKL = 3*ATILE, SVH = 4*ATILE, SVL = 5*ATILE;

    int tid  = threadIdx.x;
    int lane = tid & 31;
    int wid  = tid >> 5;               // 0..3, warp owns rows wid*16..+15
    int bh   = blockIdx.y;
    int b    = bh >> 4;
    int h    = bh & (NH_ - 1);
    int qt   = gridDim.x - 1 - blockIdx.x;   // big tiles first

    // ---- load Q tile (64 x 64 bf16, hi/lo) ----
    #pragma unroll
    for (int p = 0; p < 4; p++) {
        int f = tid + 128 * p;         // 0..511 uint4 slots
        int r = f >> 3;
        int j = f & 7;
        size_t gq = (size_t)(b * T_ + qt * 64 + r) * C_ + h * HD_ + j * 8;
        uint32_t d = r * ATRS + j * 16;
        *(uint4*)(asm_ + SQH + d) = *(const uint4*)(qh + gq);
        *(uint4*)(asm_ + SQL + d) = *(const uint4*)(ql + gq);
    }

    float m0 = -1e30f, m1 = -1e30f, l0 = 0.f, l1 = 0.f;
    float O[8][4];
    #pragma unroll
    for (int nt = 0; nt < 8; nt++)
        #pragma unroll
        for (int r = 0; r < 4; r++) O[nt][r] = 0.f;

    const __nv_bfloat16* khb = kh + (size_t)(b * T_) * C_ + h * HD_;
    const __nv_bfloat16* klb = kl + (size_t)(b * T_) * C_ + h * HD_;
    const __nv_bfloat16* vhb = vth + (size_t)bh * HD_ * T_;
    const __nv_bfloat16* vlb = vtl + (size_t)bh * HD_ * T_;

    for (int jt = 0; jt <= qt; jt++) {
        __syncthreads();   // prior iter done with K/V smem (also orders Q load on jt=0)
        #pragma unroll
        for (int p = 0; p < 4; p++) {
            int f = tid + 128 * p;
            int r = f >> 3;
            int j = f & 7;
            uint32_t d = r * ATRS + j * 16;
            size_t gk = (size_t)(jt * 64 + r) * C_ + j * 8;
            *(uint4*)(asm_ + SKH + d) = *(const uint4*)(khb + gk);
            *(uint4*)(asm_ + SKL + d) = *(const uint4*)(klb + gk);
            size_t gv = (size_t)r * T_ + jt * 64 + j * 8;
            *(uint4*)(asm_ + SVH + d) = *(const uint4*)(vhb + gv);
            *(uint4*)(asm_ + SVL + d) = *(const uint4*)(vlb + gv);
        }
        __syncthreads();

        // ---- S = Q K^T (3-term split) ----
        float S[8][4];
        #pragma unroll
        for (int nt = 0; nt < 8; nt++)
            #pragma unroll
            for (int r = 0; r < 4; r++) S[nt][r] = 0.f;

        #pragma unroll
        for (int ks = 0; ks < 4; ks++) {
            int mrow = wid * 16 + (lane & 15);
            uint32_t qa = sb + SQH + mrow * ATRS + ks * 32 + (lane >> 4) * 16;
            uint32_t qah[4], qal[4];
            LDSM_X4(qah[0], qah[1], qah[2], qah[3], qa);
            LDSM_X4(qal[0], qal[1], qal[2], qal[3], qa + ATILE);
            #pragma unroll
            for (int nt2 = 0; nt2 < 4; nt2++) {
                int nrow = nt2 * 16 + (lane & 7) + ((lane >> 4) << 3);
                uint32_t ka = sb + SKH + nrow * ATRS + ks * 32 + ((lane >> 3) & 1) * 16;
                uint32_t kbh[4], kbl[4];
                LDSM_X4(kbh[0], kbh[1], kbh[2], kbh[3], ka);
                LDSM_X4(kbl[0], kbl[1], kbl[2], kbl[3], ka + ATILE);
                MMA_BF16(S[2*nt2],   qah, kbh[0], kbh[1]);
                MMA_BF16(S[2*nt2],   qah, kbl[0], kbl[1]);
                MMA_BF16(S[2*nt2],   qal, kbh[0], kbh[1]);
                MMA_BF16(S[2*nt2+1], qah, kbh[2], kbh[3]);
                MMA_BF16(S[2*nt2+1], qah, kbl[2], kbl[3]);
                MMA_BF16(S[2*nt2+1], qal, kbh[2], kbh[3]);
            }
        }

        // ---- causal mask on diagonal tile ----
        if (jt == qt) {
            int r0 = wid * 16 + (lane >> 2);
            int r1 = r0 + 8;
            #pragma unroll
            for (int nt = 0; nt < 8; nt++) {
                int c0 = nt * 8 + (lane & 3) * 2;
                if (c0     > r0) S[nt][0] = -1e30f;
                if (c0 + 1 > r0) S[nt][1] = -1e30f;
                if (c0     > r1) S[nt][2] = -1e30f;
                if (c0 + 1 > r1) S[nt][3] = -1e30f;
            }
        }

        // ---- online softmax (rows r0 = lane>>2, r1 = r0+8) ----
        float rmax0 = -1e30f, rmax1 = -1e30f;
        #pragma unroll
        for (int nt = 0; nt < 8; nt++) {
            rmax0 = fmaxf(rmax0, fmaxf(S[nt][0], S[nt][1]));
            rmax1 = fmaxf(rmax1, fmaxf(S[nt][2], S[nt][3]));
        }
        rmax0 = fmaxf(rmax0, __shfl_xor_sync(0xffffffffu, rmax0, 1));
        rmax0 = fmaxf(rmax0, __shfl_xor_sync(0xffffffffu, rmax0, 2));
        rmax1 = fmaxf(rmax1, __shfl_xor_sync(0xffffffffu, rmax1, 1));
        rmax1 = fmaxf(rmax1, __shfl_xor_sync(0xffffffffu, rmax1, 2));
        float mn0 = fmaxf(m0, rmax0), mn1 = fmaxf(m1, rmax1);
        float al0 = __expf(m0 - mn0), al1 = __expf(m1 - mn1);
        m0 = mn0; m1 = mn1;
        float sum0 = 0.f, sum1 = 0.f;
        #pragma unroll
        for (int nt = 0; nt < 8; nt++) {
            S[nt][0] = __expf(S[nt][0] - mn0); sum0 += S[nt][0];
            S[nt][1] = __expf(S[nt][1] - mn0); sum0 += S[nt][1];
            S[nt][2] = __expf(S[nt][2] - mn1); sum1 += S[nt][2];
            S[nt][3] = __expf(S[nt][3] - mn1); sum1 += S[nt][3];
        }
        sum0 += __shfl_xor_sync(0xffffffffu, sum0, 1);
        sum0 += __shfl_xor_sync(0xffffffffu, sum0, 2);
        sum1 += __shfl_xor_sync(0xffffffffu, sum1, 1);
        sum1 += __shfl_xor_sync(0xffffffffu, sum1, 2);
        l0 = l0 * al0 + sum0;
        l1 = l1 * al1 + sum1;
        #pragma unroll
        for (int nt = 0; nt < 8; nt++) {
            O[nt][0] *= al0; O[nt][1] *= al0;
            O[nt][2] *= al1; O[nt][3] *= al1;
        }

        // ---- O += P V (3-term split; S c-frags reused as A-frags) ----
        #pragma unroll
        for (int ks = 0; ks < 4; ks++) {
            uint32_t pah[4], pal[4];
            split2(S[2*ks][0],   S[2*ks][1],   pah[0], pal[0]);
            split2(S[2*ks][2],   S[2*ks][3],   pah[1], pal[1]);
            split2(S[2*ks+1][0], S[2*ks+1][1], pah[2], pal[2]);
            split2(S[2*ks+1][2], S[2*ks+1][3], pah[3], pal[3]);
            #pragma unroll
            for (int nt2 = 0; nt2 < 4; nt2++) {
                int nrow = nt2 * 16 + (lane & 7) + ((lane >> 4) << 3);
                uint32_t va = sb + SVH + nrow * ATRS + ks * 32 + ((lane >> 3) & 1) * 16;
                uint32_t vbh[4], vbl[4];
                LDSM_X4(vbh[0], vbh[1], vbh[2], vbh[3], va);
                LDSM_X4(vbl[0], vbl[1], vbl[2], vbl[3], va + ATILE);
                MMA_BF16(O[2*nt2],   pah, vbh[0], vbh[1]);
                MMA_BF16(O[2*nt2],   pah, vbl[0], vbl[1]);
                MMA_BF16(O[2*nt2],   pal, vbh[0], vbh[1]);
                MMA_BF16(O[2*nt2+1], pah, vbh[2], vbh[3]);
                MMA_BF16(O[2*nt2+1], pah, vbl[2], vbl[3]);
                MMA_BF16(O[2*nt2+1], pal, vbh[2], vbh[3]);
            }
        }
    }

    // ---- epilogue: normalize, split, store ----
    float invl0 = 1.0f / l0;
    float invl1 = 1.0f / l1;
    int trow0 = qt * 64 + wid * 16 + (lane >> 2);
    int trow1 = trow0 + 8;
    #pragma unroll
    for (int nt = 0; nt < 8; nt++) {
        int col = h * HD_ + nt * 8 + (lane & 3) * 2;
        uint32_t hw, lw;
        split2(O[nt][0] * invl0, O[nt][1] * invl0, hw, lw);
        size_t o1 = (size_t)(b * T_ + trow0) * C_ + col;
        *(uint32_t*)(oh + o1) = hw;
        *(uint32_t*)(ol + o1) = lw;
        split2(O[nt][2] * invl1, O[nt][3] * invl1, hw, lw);
        size_t o2 = (size_t)(b * T_ + trow1) * C_ + col;
        *(uint32_t*)(oh + o2) = hw;
        *(uint32_t*)(ol + o2) = lw;
    }
}

// ---------------- SiLU(a) * b -> split bf16 hi/lo ----------------
__global__ __launch_bounds__(256) void silu_mul_split_k(const float* __restrict__ a,
                                                        const float* __restrict__ b,
                                                        __nv_bfloat16* __restrict__ sh,
                                                        __nv_bfloat16* __restrict__ sl)
{
    int i = blockIdx.x * blockDim.x + threadIdx.x;
    float4 av = ((const float4*)a)[i];
    float4 bv = ((const float4*)b)[i];
    float y0 = av.x / (1.0f + expf(-av.x)) * bv.x;
    float y1 = av.y / (1.0f + expf(-av.y)) * bv.y;
    float y2 = av.z / (1.0f + expf(-av.z)) * bv.z;
    float y3 = av.w / (1.0f + expf(-av.w)) * bv.w;
    uint32_t h0, l0, h1, l1;
    split2(y0, y1, h0, l0);
    split2(y2, y3, h1, l1);
    size_t off = (size_t)i * 4;
    *(uint2*)(sh + off) = make_uint2(h0, h1);
    *(uint2*)(sl + off) = make_uint2(l0, l1);
}

// ---------------- launch ----------------
extern "C" void kernel_launch(void* const* d_in, const int* in_sizes, int n_in,
                              void* d_out, int out_size)
{
    const float* x  = (const float*)d_in[0];
    const float* g1 = (const float*)d_in[2];
    const float* wq = (const float*)d_in[3];
    const float* wk = (const float*)d_in[4];
    const float* wv = (const float*)d_in[5];
    const float* wo = (const float*)d_in[6];
    const float* g2 = (const float*)d_in[7];
    const float* w1 = (const float*)d_in[8];
    const float* w2 = (const float*)d_in[9];
    const float* w3 = (const float*)d_in[10];
    float* out = (float*)d_out;

    float *q, *k, *v, *x2, *a, *bb;
    __nv_bfloat16 *wth, *wtl, *hh, *hl, *oh, *ol, *sh, *sl;
    __nv_bfloat16 *qh, *ql, *kh, *kl, *vth, *vtl;
    cudaGetSymbolAddress((void**)&q,   g_q);
    cudaGetSymbolAddress((void**)&k,   g_k);
    cudaGetSymbolAddress((void**)&v,   g_v);
    cudaGetSymbolAddress((void**)&x2,  g_x2);
    cudaGetSymbolAddress((void**)&a,   g_a);
    cudaGetSymbolAddress((void**)&bb,  g_b);
    cudaGetSymbolAddress((void**)&wth, g_wth);
    cudaGetSymbolAddress((void**)&wtl, g_wtl);
    cudaGetSymbolAddress((void**)&hh,  g_hh);
    cudaGetSymbolAddress((void**)&hl,  g_hl);
    cudaGetSymbolAddress((void**)&oh,  g_oh);
    cudaGetSymbolAddress((void**)&ol,  g_ol);
    cudaGetSymbolAddress((void**)&sh,  g_sh);
    cudaGetSymbolAddress((void**)&sl,  g_sl);
    cudaGetSymbolAddress((void**)&qh,  g_qh);
    cudaGetSymbolAddress((void**)&ql,  g_ql);
    cudaGetSymbolAddress((void**)&kh,  g_kh);
    cudaGetSymbolAddress((void**)&kl,  g_kl);
    cudaGetSymbolAddress((void**)&vth, g_vth);
    cudaGetSymbolAddress((void**)&vtl, g_vtl);

    cudaFuncSetAttribute(tgemm_k,    cudaFuncAttributeMaxDynamicSharedMemorySize, TG_SMEM);
    cudaFuncSetAttribute(attn_mma_k, cudaFuncAttributeMaxDynamicSharedMemorySize, AT_SMEM);

    // 0. transpose + hi/lo split all weights
    dim3 wb(32, 8);
    wsplit_k<<<dim3(C_/32,  C_/32),  wb>>>(wq, wth + WOFF_Q, wtl + WOFF_Q, C_,  C_);
    wsplit_k<<<dim3(C_/32,  C_/32),  wb>>>(wk, wth + WOFF_K, wtl + WOFF_K, C_,  C_);
    wsplit_k<<<dim3(C_/32,  C_/32),  wb>>>(wv, wth + WOFF_V, wtl + WOFF_V, C_,  C_);
    wsplit_k<<<dim3(C_/32,  C_/32),  wb>>>(wo, wth + WOFF_O, wtl + WOFF_O, C_,  C_);
    wsplit_k<<<dim3(FF_/32, C_/32),  wb>>>(w1, wth + WOFF_1, wtl + WOFF_1, C_,  FF_);
    wsplit_k<<<dim3(FF_/32, C_/32),  wb>>>(w3, wth + WOFF_3, wtl + WOFF_3, C_,  FF_);
    wsplit_k<<<dim3(C_/32,  FF_/32), wb>>>(w2, wth + WOFF_2, wtl + WOFF_2, FF_, C_);

    // 1. h = rmsnorm(x, g1) -> split
    rmsnorm_split_k<<<M_, 256>>>(x, g1, hh, hl);

    // 2. q,k,v = h @ {wq,wk,wv}
    dim3 gC(C_ / 128, M_ / 128);
    tgemm_k<<<gC, 256, TG_SMEM>>>(hh, hl, wth + WOFF_Q, wtl + WOFF_Q, nullptr, q, M_, C_, C_);
    tgemm_k<<<gC, 256, TG_SMEM>>>(hh, hl, wth + WOFF_K, wtl + WOFF_K, nullptr, k, M_, C_, C_);
    tgemm_k<<<gC, 256, TG_SMEM>>>(hh, hl, wth + WOFF_V, wtl + WOFF_V, nullptr, v, M_, C_, C_);

    // 3. RoPE + split q,k;  transpose + split v
    rope_split_k<<<(M_ * NH_ * 32) / 256, 256>>>(q, k, qh, ql, kh, kl);
    vtsplit_k<<<dim3(T_/32, HD_/32, B_*NH_), wb>>>(v, vth, vtl);

    // 4. causal flash attention on tensor cores -> split o
    attn_mma_k<<<dim3(T_/64, B_*NH_), 128, AT_SMEM>>>(qh, ql, kh, kl, vth, vtl, oh, ol);

    // 5. x2 = x + o @ wo
    tgemm_k<<<gC, 256, TG_SMEM>>>(oh, ol, wth + WOFF_O, wtl + WOFF_O, x, x2, M_, C_, C_);

    // 6. h2 = rmsnorm(x2, g2) -> split
    rmsnorm_split_k<<<M_, 256>>>(x2, g2, hh, hl);

    // 7. a = h2 @ w1 ; bb = h2 @ w3 ; s = silu(a) * bb -> split
    dim3 gF(FF_ / 128, M_ / 128);
    tgemm_k<<<gF, 256, TG_SMEM>>>(hh, hl, wth + WOFF_1, wtl + WOFF_1, nullptr, a,  M_, FF_, C_);
    tgemm_k<<<gF, 256, TG_SMEM>>>(hh, hl, wth + WOFF_3, wtl + WOFF_3, nullptr, bb, M_, FF_, C_);
    silu_mul_split_k<<<(M_ * FF_ / 4) / 256, 256>>>(a, bb, sh, sl);

    // 8. out = x2 + s @ w2
    tgemm_k<<<gC, 256, TG_SMEM>>>(sh, sl, wth + WOFF_2, wtl + WOFF_2, x2, out, M_, C_, FF_);
}